// round 12
// baseline (speedup 1.0000x reference)
#include <cuda_runtime.h>
#include <cuda_bf16.h>
#include <cuda_fp16.h>
#include <cstdint>

// GraphSAGE 2-layer + head.  (Resubmit of R11 — infra failure, never ran.)
// Edge phase: CSR build (int atomics) + warp-per-node mean aggregation.
// Aggregation gathers FP16 feature rows (256B/edge, half the L2 traffic of
// fp32); accumulation + mean stay fp32. x is converted once; h1's fp16 copy
// is written by GEMM-1's epilogue for free.
// GEMMs: warp-level mma.sync bf16x3 split precision, fp32 accumulators,
// M-tile=64 (102KB smem -> 2 CTAs/SM: fill of one CTA overlaps MMA of other).

#define MAXN 100000
#define MAXE 1600000
#define DIM  128
#define SCAN_BS 1024
#define MAX_BLKS 256

typedef unsigned int u32;
typedef unsigned long long u64;

// ---- GEMM smem layout (bytes). Row pitch 136 bf16 = 272B.
#define PITCHB 272
#define AIMG_BYTES (64 * PITCHB)          // 17408 (A tile: 64 rows)
#define BIMG_BYTES (128 * PITCHB)         // 34816 (B tile: 128 rows)
#define A_HI 0
#define A_LO AIMG_BYTES
#define B_HI (2 * AIMG_BYTES)
#define B_LO (2 * AIMG_BYTES + BIMG_BYTES)
#define SMEM_GEMM (2 * AIMG_BYTES + 2 * BIMG_BYTES)   // 104448

__device__ int    g_is64;
__device__ int    g_deg[MAXN];
__device__ int    g_off[MAXN + 1];
__device__ int    g_cur[MAXN];
__device__ int    g_csr[MAXE];
__device__ int    g_part[MAX_BLKS];
__device__ float4 g_mean4[(size_t)MAXN * 32];
__device__ float4 g_h14[(size_t)MAXN * 32];
__device__ float4 g_h24[(size_t)MAXN * 32];
__device__ uint2  g_xh[(size_t)MAXN * 32];     // fp16 image of x   (8B/lane)
__device__ uint2  g_h1h[(size_t)MAXN * 32];    // fp16 image of h1
__device__ uint4  g_wimg[8][BIMG_BYTES / 16];  // bf16 weight images, pitch-136

// ---------------------------------------------------------------------------
__device__ __forceinline__ u32 smem_u32(const void* p) {
    u32 a;
    asm("{ .reg .u64 t; cvta.to.shared.u64 t, %1; cvt.u32.u64 %0, t; }"
        : "=r"(a) : "l"(p));
    return a;
}
__device__ __forceinline__ void ldsm4(u32& r0, u32& r1, u32& r2, u32& r3, u32 a) {
    asm volatile("ldmatrix.sync.aligned.m8n8.x4.shared.b16 {%0,%1,%2,%3}, [%4];"
                 : "=r"(r0), "=r"(r1), "=r"(r2), "=r"(r3) : "r"(a));
}
__device__ __forceinline__ void mma_bf16(float* d, const u32* a, u32 b0, u32 b1) {
    asm volatile(
        "mma.sync.aligned.m16n8k16.row.col.f32.bf16.bf16.f32 "
        "{%0,%1,%2,%3},{%4,%5,%6,%7},{%8,%9},{%0,%1,%2,%3};"
        : "+f"(d[0]), "+f"(d[1]), "+f"(d[2]), "+f"(d[3])
        : "r"(a[0]), "r"(a[1]), "r"(a[2]), "r"(a[3]), "r"(b0), "r"(b1));
}
__device__ __forceinline__ void cpa16(u32 s, const void* g) {
    asm volatile("cp.async.cg.shared.global [%0], [%1], 16;" :: "r"(s), "l"(g));
}
__device__ __forceinline__ void cpa_commit_wait() {
    asm volatile("cp.async.commit_group;" ::: "memory");
    asm volatile("cp.async.wait_group 0;" ::: "memory");
}
__device__ __forceinline__ void split2(float f0, float f1, u32& hp, u32& lp) {
    __nv_bfloat16 h0 = __float2bfloat16_rn(f0);
    __nv_bfloat16 h1 = __float2bfloat16_rn(f1);
    __nv_bfloat16 l0 = __float2bfloat16_rn(f0 - __bfloat162float(h0));
    __nv_bfloat16 l1 = __float2bfloat16_rn(f1 - __bfloat162float(h1));
    __nv_bfloat162 hh = __halves2bfloat162(h0, h1);
    __nv_bfloat162 ll = __halves2bfloat162(l0, l1);
    hp = *reinterpret_cast<u32*>(&hh);
    lp = *reinterpret_cast<u32*>(&ll);
}
__device__ __forceinline__ void split8(const float* f, u32* hp, u32* lp) {
    #pragma unroll
    for (int i = 0; i < 4; i++) split2(f[2 * i], f[2 * i + 1], hp[i], lp[i]);
}
__device__ __forceinline__ u32 h2bits(__half2 h) {
    return *reinterpret_cast<u32*>(&h);
}

// ---------------------------------------------------------------------------
// edge-index dtype detection (JAX silently demotes int64 randint to int32)
// ---------------------------------------------------------------------------
__global__ void detect_kernel(const int* __restrict__ w, int e) {
    if (threadIdx.x == 0 && blockIdx.x == 0) {
        int is64 = 1;
        int nchk = (e < 256) ? e : 256;
        for (int i = 0; i < nchk; i++)
            if (w[2 * i + 1] != 0) { is64 = 0; break; }
        g_is64 = is64;
    }
}

__global__ void clear_deg_kernel(int n) {
    int i = blockIdx.x * blockDim.x + threadIdx.x;
    if (i < n) g_deg[i] = 0;
}

__global__ void hist_kernel(const void* __restrict__ ei, int e, int n) {
    int i = blockIdx.x * blockDim.x + threadIdx.x;
    if (i >= e) return;
    int d = g_is64 ? (int)((const long long*)ei)[e + i] : ((const int*)ei)[e + i];
    if ((unsigned)d < (unsigned)n) atomicAdd(&g_deg[d], 1);
}

// ---------------------------------------------------------------------------
// 3-phase parallel scan
// ---------------------------------------------------------------------------
__global__ void scan_part_kernel(int n) {
    __shared__ int ws[32];
    int i = blockIdx.x * SCAN_BS + threadIdx.x;
    int lane = threadIdx.x & 31, wid = threadIdx.x >> 5;
    int v = (i < n) ? g_deg[i] : 0;
    #pragma unroll
    for (int d = 16; d; d >>= 1) v += __shfl_down_sync(0xffffffffu, v, d);
    if (lane == 0) ws[wid] = v;
    __syncthreads();
    if (wid == 0) {
        int t = ws[lane];
        #pragma unroll
        for (int d = 16; d; d >>= 1) t += __shfl_down_sync(0xffffffffu, t, d);
        if (lane == 0) g_part[blockIdx.x] = t;
    }
}

__global__ void scan_top_kernel(int nblk, int n) {
    __shared__ int wsum[32];
    int tid = threadIdx.x, lane = tid & 31, wid = tid >> 5;
    int v = (tid < nblk) ? g_part[tid] : 0;
    int s = v;
    #pragma unroll
    for (int d = 1; d < 32; d <<= 1) {
        int t = __shfl_up_sync(0xffffffffu, s, d);
        if (lane >= d) s += t;
    }
    if (lane == 31) wsum[wid] = s;
    __syncthreads();
    if (wid == 0) {
        int w2 = wsum[lane];
        #pragma unroll
        for (int d = 1; d < 32; d <<= 1) {
            int t = __shfl_up_sync(0xffffffffu, w2, d);
            if (lane >= d) w2 += t;
        }
        wsum[lane] = w2;
    }
    __syncthreads();
    int warp_base = (wid > 0) ? wsum[wid - 1] : 0;
    int incl = warp_base + s;
    if (tid < nblk) g_part[tid] = incl - v;
    if (tid == 1023) g_off[n] = incl;
}

__global__ void scan_apply_kernel(int n) {
    __shared__ int wsum[32];
    int tid = threadIdx.x, lane = tid & 31, wid = tid >> 5;
    int i = blockIdx.x * SCAN_BS + tid;
    int v = (i < n) ? g_deg[i] : 0;
    int s = v;
    #pragma unroll
    for (int d = 1; d < 32; d <<= 1) {
        int t = __shfl_up_sync(0xffffffffu, s, d);
        if (lane >= d) s += t;
    }
    if (lane == 31) wsum[wid] = s;
    __syncthreads();
    if (wid == 0) {
        int w2 = wsum[lane];
        #pragma unroll
        for (int d = 1; d < 32; d <<= 1) {
            int t = __shfl_up_sync(0xffffffffu, w2, d);
            if (lane >= d) w2 += t;
        }
        wsum[lane] = w2;
    }
    __syncthreads();
    int warp_base = (wid > 0) ? wsum[wid - 1] : 0;
    int excl = g_part[blockIdx.x] + warp_base + s - v;
    if (i < n) { g_off[i] = excl; g_cur[i] = excl; }
}

__global__ void scatter_kernel(const void* __restrict__ ei, int e, int n) {
    int i = blockIdx.x * blockDim.x + threadIdx.x;
    if (i >= e) return;
    int s, d;
    if (g_is64) {
        s = (int)((const long long*)ei)[i];
        d = (int)((const long long*)ei)[e + i];
    } else {
        s = ((const int*)ei)[i];
        d = ((const int*)ei)[e + i];
    }
    if ((unsigned)d >= (unsigned)n || (unsigned)s >= (unsigned)n) return;
    int pos = atomicAdd(&g_cur[d], 1);
    g_csr[pos] = s;
}

// ---------------------------------------------------------------------------
// x -> fp16 image (each thread converts 8 floats)
// ---------------------------------------------------------------------------
__global__ void x2h_kernel(const float4* __restrict__ x, int n16) {
    int i = blockIdx.x * blockDim.x + threadIdx.x;
    if (i >= n16) return;
    float4 v0 = x[2 * i], v1 = x[2 * i + 1];
    uint2 o0, o1;
    o0.x = h2bits(__floats2half2_rn(v0.x, v0.y));
    o0.y = h2bits(__floats2half2_rn(v0.z, v0.w));
    o1.x = h2bits(__floats2half2_rn(v1.x, v1.y));
    o1.y = h2bits(__floats2half2_rn(v1.z, v1.w));
    g_xh[2 * i] = o0;
    g_xh[2 * i + 1] = o1;
}

// ---------------------------------------------------------------------------
// mean aggregation over fp16 rows: one warp per dst node, lane = 4 dims (8B),
// unroll-8 gather, fp32 accumulation, fp32 mean output.
// ---------------------------------------------------------------------------
__global__ void aggregate_kernel(const uint2* __restrict__ feat,
                                 float4* __restrict__ outp, int n) {
    int w = (blockIdx.x * blockDim.x + threadIdx.x) >> 5;
    int lane = threadIdx.x & 31;
    if (w >= n) return;
    int s0 = g_off[w], s1 = g_off[w + 1];
    float4 a = make_float4(0.f, 0.f, 0.f, 0.f);
    int e = s0;
    for (; e + 8 <= s1; e += 8) {
        uint2 u[8];
        #pragma unroll
        for (int q = 0; q < 8; q++)
            u[q] = feat[(size_t)g_csr[e + q] * 32 + lane];
        #pragma unroll
        for (int q = 0; q < 8; q++) {
            float2 f0 = __half22float2(*reinterpret_cast<__half2*>(&u[q].x));
            float2 f1 = __half22float2(*reinterpret_cast<__half2*>(&u[q].y));
            a.x += f0.x; a.y += f0.y; a.z += f1.x; a.w += f1.y;
        }
    }
    for (; e < s1; e++) {
        uint2 u = feat[(size_t)g_csr[e] * 32 + lane];
        float2 f0 = __half22float2(*reinterpret_cast<__half2*>(&u.x));
        float2 f1 = __half22float2(*reinterpret_cast<__half2*>(&u.y));
        a.x += f0.x; a.y += f0.y; a.z += f1.x; a.w += f1.y;
    }
    int deg = s1 - s0;
    float inv = 1.0f / (float)(deg > 1 ? deg : 1);
    a.x *= inv; a.y *= inv; a.z *= inv; a.w *= inv;
    outp[(size_t)w * 32 + lane] = a;
}

// ---------------------------------------------------------------------------
// weight prep: split 128x128 fp32 W into bf16 hi/lo pitch-136 images.
// ---------------------------------------------------------------------------
__global__ void wprep_kernel(const float* __restrict__ Wl1,
                             const float* __restrict__ Wr1,
                             const float* __restrict__ Wl2,
                             const float* __restrict__ Wr2) {
    const float* Wm[4] = {Wl1, Wr1, Wl2, Wr2};
    int m = blockIdx.x;
    const float* W = Wm[m];
    char* hi_img = (char*)&g_wimg[2 * m][0];
    char* lo_img = (char*)&g_wimg[2 * m + 1][0];
    for (int g = threadIdx.x; g < 2048; g += blockDim.x) {
        int row = g >> 4;
        int col8 = (g & 15) << 3;
        float f[8];
        #pragma unroll
        for (int i = 0; i < 8; i++) f[i] = W[row * 128 + col8 + i];
        u32 hp[4], lp[4];
        split8(f, hp, lp);
        int off = row * PITCHB + col8 * 2;
        *reinterpret_cast<uint4*>(hi_img + off) = make_uint4(hp[0], hp[1], hp[2], hp[3]);
        *reinterpret_cast<uint4*>(lo_img + off) = make_uint4(lp[0], lp[1], lp[2], lp[3]);
    }
}

// ---------------------------------------------------------------------------
// mma.sync dual GEMM: C = relu(A1@Wl^T + A2@Wr^T + bias), M-tile=64, N=128.
// 256 threads, 8 warps (2x4), warp tile 32x32. bf16x3, fp32 accumulators.
// Ch (optional): fp16 copy of C for the next layer's gather.
// ---------------------------------------------------------------------------
__global__ __launch_bounds__(256) void gemm_mma_kernel(
    const float* __restrict__ A1, const float* __restrict__ A2,
    int imgbase, const float* __restrict__ bias,
    float* __restrict__ C, u32* __restrict__ Ch, int n, int do_relu) {
    extern __shared__ __align__(16) char smem[];
    u32 sbase = smem_u32(smem);
    int tid = threadIdx.x, wid = tid >> 5, lane = tid & 31;
    int row0 = blockIdx.x * 64;
    int wr = (wid >> 2) * 32;          // warp row offset (0,32)
    int wc = (wid & 3) * 32;           // warp col offset (0,32,64,96)

    float acc[2][4][4];
    #pragma unroll
    for (int a = 0; a < 2; a++)
        #pragma unroll
        for (int b = 0; b < 4; b++)
            #pragma unroll
            for (int c = 0; c < 4; c++) acc[a][b][c] = 0.f;

    #pragma unroll 1
    for (int p = 0; p < 2; p++) {
        __syncthreads();   // previous-phase ldsm reads done before overwrite
        // ---- kick weight-image copies first (cp.async overlaps with cvt) --
        {
            const uint4* bh = g_wimg[imgbase + 2 * p];
            const uint4* bl = g_wimg[imgbase + 2 * p + 1];
            for (int g = tid; g < BIMG_BYTES / 16; g += 256) {
                cpa16(sbase + B_HI + g * 16, bh + g);
                cpa16(sbase + B_LO + g * 16, bl + g);
            }
        }
        // ---- convert A slab (fp32 -> bf16 hi/lo, pitch-136), 64 rows ----
        const float* A = (p == 0) ? A1 : A2;
        for (int g = tid; g < 1024; g += 256) {
            int row = g >> 4;
            int col8 = (g & 15) << 3;
            int gr = row0 + row;
            float f[8] = {0.f, 0.f, 0.f, 0.f, 0.f, 0.f, 0.f, 0.f};
            if (gr < n) {
                float4 v0 = *reinterpret_cast<const float4*>(&A[(size_t)gr * 128 + col8]);
                float4 v1 = *reinterpret_cast<const float4*>(&A[(size_t)gr * 128 + col8 + 4]);
                f[0] = v0.x; f[1] = v0.y; f[2] = v0.z; f[3] = v0.w;
                f[4] = v1.x; f[5] = v1.y; f[6] = v1.z; f[7] = v1.w;
            }
            u32 hp[4], lp[4];
            split8(f, hp, lp);
            int off = row * PITCHB + col8 * 2;
            *reinterpret_cast<uint4*>(smem + A_HI + off) =
                make_uint4(hp[0], hp[1], hp[2], hp[3]);
            *reinterpret_cast<uint4*>(smem + A_LO + off) =
                make_uint4(lp[0], lp[1], lp[2], lp[3]);
        }
        cpa_commit_wait();
        __syncthreads();

        // ---- MMA mainloop over K ----
        int lr = lane & 15;            // ldmatrix row within 16
        int lc = (lane >> 4) * 8;      // ldmatrix col half
        #pragma unroll 1
        for (int k0 = 0; k0 < 128; k0 += 16) {
            u32 ah[2][4], al[2][4], bh[2][4], bl[2][4];
            #pragma unroll
            for (int mf = 0; mf < 2; mf++) {
                u32 ad = sbase + A_HI + (wr + mf * 16 + lr) * PITCHB + (k0 + lc) * 2;
                ldsm4(ah[mf][0], ah[mf][1], ah[mf][2], ah[mf][3], ad);
                ldsm4(al[mf][0], al[mf][1], al[mf][2], al[mf][3],
                      ad + (A_LO - A_HI));
            }
            #pragma unroll
            for (int q = 0; q < 2; q++) {
                u32 bd = sbase + B_HI + (wc + q * 16 + lr) * PITCHB + (k0 + lc) * 2;
                ldsm4(bh[q][0], bh[q][1], bh[q][2], bh[q][3], bd);
                ldsm4(bl[q][0], bl[q][1], bl[q][2], bl[q][3], bd + (B_LO - B_HI));
            }
            #pragma unroll
            for (int mf = 0; mf < 2; mf++)
                #pragma unroll
                for (int nf = 0; nf < 4; nf++) {
                    int q = nf >> 1, h = nf & 1;
                    mma_bf16(acc[mf][nf], ah[mf], bh[q][h], bh[q][h + 2]);
                    mma_bf16(acc[mf][nf], al[mf], bh[q][h], bh[q][h + 2]);
                    mma_bf16(acc[mf][nf], ah[mf], bl[q][h], bl[q][h + 2]);
                }
        }
    }

    // ---- epilogue: bias + relu + store (fp32, plus optional fp16 copy) ----
    #pragma unroll
    for (int mf = 0; mf < 2; mf++) {
        int rb = row0 + wr + mf * 16 + (lane >> 2);
        #pragma unroll
        for (int nf = 0; nf < 4; nf++) {
            int cn = wc + nf * 8 + (lane & 3) * 2;
            float b0 = __ldg(&bias[cn]), b1 = __ldg(&bias[cn + 1]);
            float v0 = acc[mf][nf][0] + b0, v1 = acc[mf][nf][1] + b1;
            float v2 = acc[mf][nf][2] + b0, v3 = acc[mf][nf][3] + b1;
            if (do_relu) {
                v0 = v0 < 0.f ? 0.f : v0; v1 = v1 < 0.f ? 0.f : v1;
                v2 = v2 < 0.f ? 0.f : v2; v3 = v3 < 0.f ? 0.f : v3;
            }
            if (rb < n) {
                *reinterpret_cast<float2*>(&C[(size_t)rb * 128 + cn]) =
                    make_float2(v0, v1);
                if (Ch) Ch[(size_t)rb * 64 + (cn >> 1)] =
                    h2bits(__floats2half2_rn(v0, v1));
            }
            if (rb + 8 < n) {
                *reinterpret_cast<float2*>(&C[(size_t)(rb + 8) * 128 + cn]) =
                    make_float2(v2, v3);
                if (Ch) Ch[(size_t)(rb + 8) * 64 + (cn >> 1)] =
                    h2bits(__floats2half2_rn(v2, v3));
            }
        }
    }
}

// ---------------------------------------------------------------------------
// output head: out[N,40] = h2 @ Wout^T + bout.  32 nodes/block.
// ---------------------------------------------------------------------------
__global__ __launch_bounds__(256) void out_gemm_kernel(
    const float* __restrict__ h, const float* __restrict__ Wout,
    const float* __restrict__ bout, float* __restrict__ out, int n) {
    __shared__ __align__(16) float sh[32][128];
    __shared__ __align__(16) float sw[40][132];
    int tid = threadIdx.x;
    int node0 = blockIdx.x * 32;
    for (int g = tid; g < 1280; g += 256) {      // Wout: 40x128
        int j = g >> 5, k4 = (g & 31) << 2;
        float4 v = *reinterpret_cast<const float4*>(&Wout[j * 128 + k4]);
        *reinterpret_cast<float4*>(&sw[j][k4]) = v;
    }
    for (int g = tid; g < 1024; g += 256) {      // h rows: 32x128
        int r = g >> 5, k4 = (g & 31) << 2;
        int gn = node0 + r;
        float4 v = make_float4(0.f, 0.f, 0.f, 0.f);
        if (gn < n)
            v = *reinterpret_cast<const float4*>(&h[(size_t)gn * 128 + k4]);
        *reinterpret_cast<float4*>(&sh[r][k4]) = v;
    }
    __syncthreads();
    int r = tid >> 3;                 // node within block (0..31)
    int jj0 = (tid & 7) * 5;          // first of 5 output cols
    float acc[5] = {0.f, 0.f, 0.f, 0.f, 0.f};
    #pragma unroll 8
    for (int k4 = 0; k4 < 128; k4 += 4) {
        float4 hv = *reinterpret_cast<const float4*>(&sh[r][k4]);
        #pragma unroll
        for (int q = 0; q < 5; q++) {
            float4 wv = *reinterpret_cast<const float4*>(&sw[jj0 + q][k4]);
            acc[q] += hv.x * wv.x + hv.y * wv.y + hv.z * wv.z + hv.w * wv.w;
        }
    }
    int node = node0 + r;
    if (node < n) {
        #pragma unroll
        for (int q = 0; q < 5; q++)
            out[(size_t)node * 40 + jj0 + q] = acc[q] + __ldg(&bout[jj0 + q]);
    }
}

// ---------------------------------------------------------------------------
extern "C" void kernel_launch(void* const* d_in, const int* in_sizes, int n_in,
                              void* d_out, int out_size) {
    const float* x = (const float*)d_in[0];
    const void* ei = d_in[1];
    const float* Wl1 = (const float*)d_in[2];
    const float* bl1 = (const float*)d_in[3];
    const float* Wr1 = (const float*)d_in[4];
    const float* Wl2 = (const float*)d_in[5];
    const float* bl2 = (const float*)d_in[6];
    const float* Wr2 = (const float*)d_in[7];
    const float* Wout = (const float*)d_in[8];
    const float* bout = (const float*)d_in[9];
    float* out = (float*)d_out;

    int n = in_sizes[0] / DIM;
    int e = in_sizes[1] / 2;

    static float* mean_f = nullptr;
    static float* h1_f = nullptr;
    static float* h2_f = nullptr;
    static uint2* xh_p = nullptr;
    static uint2* h1h_p = nullptr;
    if (!mean_f) {  // one-time symbol lookup + smem attribute (no allocation)
        void* p;
        cudaGetSymbolAddress(&p, g_mean4); mean_f = (float*)p;
        cudaGetSymbolAddress(&p, g_h14);   h1_f   = (float*)p;
        cudaGetSymbolAddress(&p, g_h24);   h2_f   = (float*)p;
        cudaGetSymbolAddress(&p, g_xh);    xh_p   = (uint2*)p;
        cudaGetSymbolAddress(&p, g_h1h);   h1h_p  = (uint2*)p;
        cudaFuncSetAttribute(gemm_mma_kernel,
                             cudaFuncAttributeMaxDynamicSharedMemorySize, SMEM_GEMM);
    }

    int eb = (e + 255) / 256;
    int nb = (n + 255) / 256;
    int sblk = (n + SCAN_BS - 1) / SCAN_BS;
    int n16 = n * 16;
    int cb = (n16 + 255) / 256;

    detect_kernel<<<1, 32>>>((const int*)ei, e);
    x2h_kernel<<<cb, 256>>>((const float4*)x, n16);
    clear_deg_kernel<<<nb, 256>>>(n);
    hist_kernel<<<eb, 256>>>(ei, e, n);
    scan_part_kernel<<<sblk, SCAN_BS>>>(n);
    scan_top_kernel<<<1, 1024>>>(sblk, n);
    scan_apply_kernel<<<sblk, SCAN_BS>>>(n);
    scatter_kernel<<<eb, 256>>>(ei, e, n);
    wprep_kernel<<<4, 256>>>(Wl1, Wr1, Wl2, Wr2);

    int ab = (n + 7) / 8;
    int gb = (n + 63) / 64;
    int ob = (n + 31) / 32;

    // Layer 1 (gather fp16 x; GEMM writes h1 + fp16 copy)
    aggregate_kernel<<<ab, 256>>>(xh_p, (float4*)mean_f, n);
    gemm_mma_kernel<<<gb, 256, SMEM_GEMM>>>(mean_f, x, 0, bl1, h1_f,
                                            (u32*)h1h_p, n, 1);
    // Layer 2 (gather fp16 h1)
    aggregate_kernel<<<ab, 256>>>(h1h_p, (float4*)mean_f, n);
    gemm_mma_kernel<<<gb, 256, SMEM_GEMM>>>(mean_f, h1_f, 4, bl2, h2_f,
                                            nullptr, n, 1);
    // Head
    out_gemm_kernel<<<ob, 256>>>(h2_f, Wout, bout, out, n);
}

// round 13
// speedup vs baseline: 1.0049x; 1.0049x over previous
#include <cuda_runtime.h>
#include <cuda_bf16.h>
#include <cuda_fp16.h>
#include <cstdint>

// GraphSAGE 2-layer + head.
// Edge phase: CSR build (int atomics) + warp-per-node mean aggregation over
// fp16 feature rows (fp32 accumulate). detect_kernel is PARALLEL (the old
// 1-thread dependent-load loop serialized ~50us of memory latency per replay).
// GEMMs: warp-level mma.sync bf16x3 split precision, fp32 accumulators,
// M-tile=64 (102KB smem -> 2 CTAs/SM: fill of one CTA overlaps MMA of other).

#define MAXN 100000
#define MAXE 1600000
#define DIM  128
#define SCAN_BS 1024
#define MAX_BLKS 256

typedef unsigned int u32;
typedef unsigned long long u64;

// ---- GEMM smem layout (bytes). Row pitch 136 bf16 = 272B.
#define PITCHB 272
#define AIMG_BYTES (64 * PITCHB)          // 17408 (A tile: 64 rows)
#define BIMG_BYTES (128 * PITCHB)         // 34816 (B tile: 128 rows)
#define A_HI 0
#define A_LO AIMG_BYTES
#define B_HI (2 * AIMG_BYTES)
#define B_LO (2 * AIMG_BYTES + BIMG_BYTES)
#define SMEM_GEMM (2 * AIMG_BYTES + 2 * BIMG_BYTES)   // 104448

__device__ int    g_is64;
__device__ int    g_deg[MAXN];
__device__ int    g_off[MAXN + 1];
__device__ int    g_cur[MAXN];
__device__ int    g_csr[MAXE];
__device__ int    g_part[MAX_BLKS];
__device__ float4 g_mean4[(size_t)MAXN * 32];
__device__ float4 g_h14[(size_t)MAXN * 32];
__device__ float4 g_h24[(size_t)MAXN * 32];
__device__ uint2  g_xh[(size_t)MAXN * 32];     // fp16 image of x   (8B/lane)
__device__ uint2  g_h1h[(size_t)MAXN * 32];    // fp16 image of h1
__device__ uint4  g_wimg[8][BIMG_BYTES / 16];  // bf16 weight images, pitch-136

// ---------------------------------------------------------------------------
__device__ __forceinline__ u32 smem_u32(const void* p) {
    u32 a;
    asm("{ .reg .u64 t; cvta.to.shared.u64 t, %1; cvt.u32.u64 %0, t; }"
        : "=r"(a) : "l"(p));
    return a;
}
__device__ __forceinline__ void ldsm4(u32& r0, u32& r1, u32& r2, u32& r3, u32 a) {
    asm volatile("ldmatrix.sync.aligned.m8n8.x4.shared.b16 {%0,%1,%2,%3}, [%4];"
                 : "=r"(r0), "=r"(r1), "=r"(r2), "=r"(r3) : "r"(a));
}
__device__ __forceinline__ void mma_bf16(float* d, const u32* a, u32 b0, u32 b1) {
    asm volatile(
        "mma.sync.aligned.m16n8k16.row.col.f32.bf16.bf16.f32 "
        "{%0,%1,%2,%3},{%4,%5,%6,%7},{%8,%9},{%0,%1,%2,%3};"
        : "+f"(d[0]), "+f"(d[1]), "+f"(d[2]), "+f"(d[3])
        : "r"(a[0]), "r"(a[1]), "r"(a[2]), "r"(a[3]), "r"(b0), "r"(b1));
}
__device__ __forceinline__ void cpa16(u32 s, const void* g) {
    asm volatile("cp.async.cg.shared.global [%0], [%1], 16;" :: "r"(s), "l"(g));
}
__device__ __forceinline__ void cpa_commit_wait() {
    asm volatile("cp.async.commit_group;" ::: "memory");
    asm volatile("cp.async.wait_group 0;" ::: "memory");
}
__device__ __forceinline__ void split2(float f0, float f1, u32& hp, u32& lp) {
    __nv_bfloat16 h0 = __float2bfloat16_rn(f0);
    __nv_bfloat16 h1 = __float2bfloat16_rn(f1);
    __nv_bfloat16 l0 = __float2bfloat16_rn(f0 - __bfloat162float(h0));
    __nv_bfloat16 l1 = __float2bfloat16_rn(f1 - __bfloat162float(h1));
    __nv_bfloat162 hh = __halves2bfloat162(h0, h1);
    __nv_bfloat162 ll = __halves2bfloat162(l0, l1);
    hp = *reinterpret_cast<u32*>(&hh);
    lp = *reinterpret_cast<u32*>(&ll);
}
__device__ __forceinline__ void split8(const float* f, u32* hp, u32* lp) {
    #pragma unroll
    for (int i = 0; i < 4; i++) split2(f[2 * i], f[2 * i + 1], hp[i], lp[i]);
}
__device__ __forceinline__ u32 h2bits(__half2 h) {
    return *reinterpret_cast<u32*>(&h);
}

// ---------------------------------------------------------------------------
// edge-index dtype detection (JAX silently demotes int64 randint to int32).
// PARALLEL: 256 threads each probe one odd 32-bit word; int64 data has all
// zero high words there.
// ---------------------------------------------------------------------------
__global__ void detect_kernel(const int* __restrict__ w, int e) {
    __shared__ int bad;
    int i = threadIdx.x;
    if (i == 0) bad = 0;
    __syncthreads();
    int nchk = (e < 256) ? e : 256;
    if (i < nchk && w[2 * i + 1] != 0) atomicOr(&bad, 1);
    __syncthreads();
    if (i == 0) g_is64 = bad ? 0 : 1;
}

__global__ void clear_deg_kernel(int n) {
    int i = blockIdx.x * blockDim.x + threadIdx.x;
    if (i < n) g_deg[i] = 0;
}

__global__ void hist_kernel(const void* __restrict__ ei, int e, int n) {
    int i = blockIdx.x * blockDim.x + threadIdx.x;
    if (i >= e) return;
    int d = g_is64 ? (int)((const long long*)ei)[e + i] : ((const int*)ei)[e + i];
    if ((unsigned)d < (unsigned)n) atomicAdd(&g_deg[d], 1);
}

// ---------------------------------------------------------------------------
// 3-phase parallel scan
// ---------------------------------------------------------------------------
__global__ void scan_part_kernel(int n) {
    __shared__ int ws[32];
    int i = blockIdx.x * SCAN_BS + threadIdx.x;
    int lane = threadIdx.x & 31, wid = threadIdx.x >> 5;
    int v = (i < n) ? g_deg[i] : 0;
    #pragma unroll
    for (int d = 16; d; d >>= 1) v += __shfl_down_sync(0xffffffffu, v, d);
    if (lane == 0) ws[wid] = v;
    __syncthreads();
    if (wid == 0) {
        int t = ws[lane];
        #pragma unroll
        for (int d = 16; d; d >>= 1) t += __shfl_down_sync(0xffffffffu, t, d);
        if (lane == 0) g_part[blockIdx.x] = t;
    }
}

__global__ void scan_top_kernel(int nblk, int n) {
    __shared__ int wsum[32];
    int tid = threadIdx.x, lane = tid & 31, wid = tid >> 5;
    int v = (tid < nblk) ? g_part[tid] : 0;
    int s = v;
    #pragma unroll
    for (int d = 1; d < 32; d <<= 1) {
        int t = __shfl_up_sync(0xffffffffu, s, d);
        if (lane >= d) s += t;
    }
    if (lane == 31) wsum[wid] = s;
    __syncthreads();
    if (wid == 0) {
        int w2 = wsum[lane];
        #pragma unroll
        for (int d = 1; d < 32; d <<= 1) {
            int t = __shfl_up_sync(0xffffffffu, w2, d);
            if (lane >= d) w2 += t;
        }
        wsum[lane] = w2;
    }
    __syncthreads();
    int warp_base = (wid > 0) ? wsum[wid - 1] : 0;
    int incl = warp_base + s;
    if (tid < nblk) g_part[tid] = incl - v;
    if (tid == 1023) g_off[n] = incl;
}

__global__ void scan_apply_kernel(int n) {
    __shared__ int wsum[32];
    int tid = threadIdx.x, lane = tid & 31, wid = tid >> 5;
    int i = blockIdx.x * SCAN_BS + tid;
    int v = (i < n) ? g_deg[i] : 0;
    int s = v;
    #pragma unroll
    for (int d = 1; d < 32; d <<= 1) {
        int t = __shfl_up_sync(0xffffffffu, s, d);
        if (lane >= d) s += t;
    }
    if (lane == 31) wsum[wid] = s;
    __syncthreads();
    if (wid == 0) {
        int w2 = wsum[lane];
        #pragma unroll
        for (int d = 1; d < 32; d <<= 1) {
            int t = __shfl_up_sync(0xffffffffu, w2, d);
            if (lane >= d) w2 += t;
        }
        wsum[lane] = w2;
    }
    __syncthreads();
    int warp_base = (wid > 0) ? wsum[wid - 1] : 0;
    int excl = g_part[blockIdx.x] + warp_base + s - v;
    if (i < n) { g_off[i] = excl; g_cur[i] = excl; }
}

__global__ void scatter_kernel(const void* __restrict__ ei, int e, int n) {
    int i = blockIdx.x * blockDim.x + threadIdx.x;
    if (i >= e) return;
    int s, d;
    if (g_is64) {
        s = (int)((const long long*)ei)[i];
        d = (int)((const long long*)ei)[e + i];
    } else {
        s = ((const int*)ei)[i];
        d = ((const int*)ei)[e + i];
    }
    if ((unsigned)d >= (unsigned)n || (unsigned)s >= (unsigned)n) return;
    int pos = atomicAdd(&g_cur[d], 1);
    g_csr[pos] = s;
}

// ---------------------------------------------------------------------------
// x -> fp16 image (each thread converts 8 floats)
// ---------------------------------------------------------------------------
__global__ void x2h_kernel(const float4* __restrict__ x, int n16) {
    int i = blockIdx.x * blockDim.x + threadIdx.x;
    if (i >= n16) return;
    float4 v0 = x[2 * i], v1 = x[2 * i + 1];
    uint2 o0, o1;
    o0.x = h2bits(__floats2half2_rn(v0.x, v0.y));
    o0.y = h2bits(__floats2half2_rn(v0.z, v0.w));
    o1.x = h2bits(__floats2half2_rn(v1.x, v1.y));
    o1.y = h2bits(__floats2half2_rn(v1.z, v1.w));
    g_xh[2 * i] = o0;
    g_xh[2 * i + 1] = o1;
}

// ---------------------------------------------------------------------------
// mean aggregation over fp16 rows: one warp per dst node, lane = 4 dims (8B),
// unroll-8 gather, fp32 accumulation, fp32 mean output.
// ---------------------------------------------------------------------------
__global__ void aggregate_kernel(const uint2* __restrict__ feat,
                                 float4* __restrict__ outp, int n) {
    int w = (blockIdx.x * blockDim.x + threadIdx.x) >> 5;
    int lane = threadIdx.x & 31;
    if (w >= n) return;
    int s0 = g_off[w], s1 = g_off[w + 1];
    float4 a = make_float4(0.f, 0.f, 0.f, 0.f);
    int e = s0;
    for (; e + 8 <= s1; e += 8) {
        uint2 u[8];
        #pragma unroll
        for (int q = 0; q < 8; q++)
            u[q] = feat[(size_t)g_csr[e + q] * 32 + lane];
        #pragma unroll
        for (int q = 0; q < 8; q++) {
            float2 f0 = __half22float2(*reinterpret_cast<__half2*>(&u[q].x));
            float2 f1 = __half22float2(*reinterpret_cast<__half2*>(&u[q].y));
            a.x += f0.x; a.y += f0.y; a.z += f1.x; a.w += f1.y;
        }
    }
    for (; e < s1; e++) {
        uint2 u = feat[(size_t)g_csr[e] * 32 + lane];
        float2 f0 = __half22float2(*reinterpret_cast<__half2*>(&u.x));
        float2 f1 = __half22float2(*reinterpret_cast<__half2*>(&u.y));
        a.x += f0.x; a.y += f0.y; a.z += f1.x; a.w += f1.y;
    }
    int deg = s1 - s0;
    float inv = 1.0f / (float)(deg > 1 ? deg : 1);
    a.x *= inv; a.y *= inv; a.z *= inv; a.w *= inv;
    outp[(size_t)w * 32 + lane] = a;
}

// ---------------------------------------------------------------------------
// weight prep: split 128x128 fp32 W into bf16 hi/lo pitch-136 images.
// ---------------------------------------------------------------------------
__global__ void wprep_kernel(const float* __restrict__ Wl1,
                             const float* __restrict__ Wr1,
                             const float* __restrict__ Wl2,
                             const float* __restrict__ Wr2) {
    const float* Wm[4] = {Wl1, Wr1, Wl2, Wr2};
    int m = blockIdx.x;
    const float* W = Wm[m];
    char* hi_img = (char*)&g_wimg[2 * m][0];
    char* lo_img = (char*)&g_wimg[2 * m + 1][0];
    for (int g = threadIdx.x; g < 2048; g += blockDim.x) {
        int row = g >> 4;
        int col8 = (g & 15) << 3;
        float f[8];
        #pragma unroll
        for (int i = 0; i < 8; i++) f[i] = W[row * 128 + col8 + i];
        u32 hp[4], lp[4];
        split8(f, hp, lp);
        int off = row * PITCHB + col8 * 2;
        *reinterpret_cast<uint4*>(hi_img + off) = make_uint4(hp[0], hp[1], hp[2], hp[3]);
        *reinterpret_cast<uint4*>(lo_img + off) = make_uint4(lp[0], lp[1], lp[2], lp[3]);
    }
}

// ---------------------------------------------------------------------------
// mma.sync dual GEMM: C = relu(A1@Wl^T + A2@Wr^T + bias), M-tile=64, N=128.
// 256 threads, 8 warps (2x4), warp tile 32x32. bf16x3, fp32 accumulators.
// Ch (optional): fp16 copy of C for the next layer's gather.
// ---------------------------------------------------------------------------
__global__ __launch_bounds__(256) void gemm_mma_kernel(
    const float* __restrict__ A1, const float* __restrict__ A2,
    int imgbase, const float* __restrict__ bias,
    float* __restrict__ C, u32* __restrict__ Ch, int n, int do_relu) {
    extern __shared__ __align__(16) char smem[];
    u32 sbase = smem_u32(smem);
    int tid = threadIdx.x, wid = tid >> 5, lane = tid & 31;
    int row0 = blockIdx.x * 64;
    int wr = (wid >> 2) * 32;          // warp row offset (0,32)
    int wc = (wid & 3) * 32;           // warp col offset (0,32,64,96)

    float acc[2][4][4];
    #pragma unroll
    for (int a = 0; a < 2; a++)
        #pragma unroll
        for (int b = 0; b < 4; b++)
            #pragma unroll
            for (int c = 0; c < 4; c++) acc[a][b][c] = 0.f;

    #pragma unroll 1
    for (int p = 0; p < 2; p++) {
        __syncthreads();   // previous-phase ldsm reads done before overwrite
        // ---- kick weight-image copies first (cp.async overlaps with cvt) --
        {
            const uint4* bh = g_wimg[imgbase + 2 * p];
            const uint4* bl = g_wimg[imgbase + 2 * p + 1];
            for (int g = tid; g < BIMG_BYTES / 16; g += 256) {
                cpa16(sbase + B_HI + g * 16, bh + g);
                cpa16(sbase + B_LO + g * 16, bl + g);
            }
        }
        // ---- convert A slab (fp32 -> bf16 hi/lo, pitch-136), 64 rows ----
        const float* A = (p == 0) ? A1 : A2;
        for (int g = tid; g < 1024; g += 256) {
            int row = g >> 4;
            int col8 = (g & 15) << 3;
            int gr = row0 + row;
            float f[8] = {0.f, 0.f, 0.f, 0.f, 0.f, 0.f, 0.f, 0.f};
            if (gr < n) {
                float4 v0 = *reinterpret_cast<const float4*>(&A[(size_t)gr * 128 + col8]);
                float4 v1 = *reinterpret_cast<const float4*>(&A[(size_t)gr * 128 + col8 + 4]);
                f[0] = v0.x; f[1] = v0.y; f[2] = v0.z; f[3] = v0.w;
                f[4] = v1.x; f[5] = v1.y; f[6] = v1.z; f[7] = v1.w;
            }
            u32 hp[4], lp[4];
            split8(f, hp, lp);
            int off = row * PITCHB + col8 * 2;
            *reinterpret_cast<uint4*>(smem + A_HI + off) =
                make_uint4(hp[0], hp[1], hp[2], hp[3]);
            *reinterpret_cast<uint4*>(smem + A_LO + off) =
                make_uint4(lp[0], lp[1], lp[2], lp[3]);
        }
        cpa_commit_wait();
        __syncthreads();

        // ---- MMA mainloop over K ----
        int lr = lane & 15;            // ldmatrix row within 16
        int lc = (lane >> 4) * 8;      // ldmatrix col half
        #pragma unroll 1
        for (int k0 = 0; k0 < 128; k0 += 16) {
            u32 ah[2][4], al[2][4], bh[2][4], bl[2][4];
            #pragma unroll
            for (int mf = 0; mf < 2; mf++) {
                u32 ad = sbase + A_HI + (wr + mf * 16 + lr) * PITCHB + (k0 + lc) * 2;
                ldsm4(ah[mf][0], ah[mf][1], ah[mf][2], ah[mf][3], ad);
                ldsm4(al[mf][0], al[mf][1], al[mf][2], al[mf][3],
                      ad + (A_LO - A_HI));
            }
            #pragma unroll
            for (int q = 0; q < 2; q++) {
                u32 bd = sbase + B_HI + (wc + q * 16 + lr) * PITCHB + (k0 + lc) * 2;
                ldsm4(bh[q][0], bh[q][1], bh[q][2], bh[q][3], bd);
                ldsm4(bl[q][0], bl[q][1], bl[q][2], bl[q][3], bd + (B_LO - B_HI));
            }
            #pragma unroll
            for (int mf = 0; mf < 2; mf++)
                #pragma unroll
                for (int nf = 0; nf < 4; nf++) {
                    int q = nf >> 1, h = nf & 1;
                    mma_bf16(acc[mf][nf], ah[mf], bh[q][h], bh[q][h + 2]);
                    mma_bf16(acc[mf][nf], al[mf], bh[q][h], bh[q][h + 2]);
                    mma_bf16(acc[mf][nf], ah[mf], bl[q][h], bl[q][h + 2]);
                }
        }
    }

    // ---- epilogue: bias + relu + store (fp32, plus optional fp16 copy) ----
    #pragma unroll
    for (int mf = 0; mf < 2; mf++) {
        int rb = row0 + wr + mf * 16 + (lane >> 2);
        #pragma unroll
        for (int nf = 0; nf < 4; nf++) {
            int cn = wc + nf * 8 + (lane & 3) * 2;
            float b0 = __ldg(&bias[cn]), b1 = __ldg(&bias[cn + 1]);
            float v0 = acc[mf][nf][0] + b0, v1 = acc[mf][nf][1] + b1;
            float v2 = acc[mf][nf][2] + b0, v3 = acc[mf][nf][3] + b1;
            if (do_relu) {
                v0 = v0 < 0.f ? 0.f : v0; v1 = v1 < 0.f ? 0.f : v1;
                v2 = v2 < 0.f ? 0.f : v2; v3 = v3 < 0.f ? 0.f : v3;
            }
            if (rb < n) {
                *reinterpret_cast<float2*>(&C[(size_t)rb * 128 + cn]) =
                    make_float2(v0, v1);
                if (Ch) Ch[(size_t)rb * 64 + (cn >> 1)] =
                    h2bits(__floats2half2_rn(v0, v1));
            }
            if (rb + 8 < n) {
                *reinterpret_cast<float2*>(&C[(size_t)(rb + 8) * 128 + cn]) =
                    make_float2(v2, v3);
                if (Ch) Ch[(size_t)(rb + 8) * 64 + (cn >> 1)] =
                    h2bits(__floats2half2_rn(v2, v3));
            }
        }
    }
}

// ---------------------------------------------------------------------------
// output head: out[N,40] = h2 @ Wout^T + bout.  32 nodes/block.
// ---------------------------------------------------------------------------
__global__ __launch_bounds__(256) void out_gemm_kernel(
    const float* __restrict__ h, const float* __restrict__ Wout,
    const float* __restrict__ bout, float* __restrict__ out, int n) {
    __shared__ __align__(16) float sh[32][128];
    __shared__ __align__(16) float sw[40][132];
    int tid = threadIdx.x;
    int node0 = blockIdx.x * 32;
    for (int g = tid; g < 1280; g += 256) {      // Wout: 40x128
        int j = g >> 5, k4 = (g & 31) << 2;
        float4 v = *reinterpret_cast<const float4*>(&Wout[j * 128 + k4]);
        *reinterpret_cast<float4*>(&sw[j][k4]) = v;
    }
    for (int g = tid; g < 1024; g += 256) {      // h rows: 32x128
        int r = g >> 5, k4 = (g & 31) << 2;
        int gn = node0 + r;
        float4 v = make_float4(0.f, 0.f, 0.f, 0.f);
        if (gn < n)
            v = *reinterpret_cast<const float4*>(&h[(size_t)gn * 128 + k4]);
        *reinterpret_cast<float4*>(&sh[r][k4]) = v;
    }
    __syncthreads();
    int r = tid >> 3;                 // node within block (0..31)
    int jj0 = (tid & 7) * 5;          // first of 5 output cols
    float acc[5] = {0.f, 0.f, 0.f, 0.f, 0.f};
    #pragma unroll 8
    for (int k4 = 0; k4 < 128; k4 += 4) {
        float4 hv = *reinterpret_cast<const float4*>(&sh[r][k4]);
        #pragma unroll
        for (int q = 0; q < 5; q++) {
            float4 wv = *reinterpret_cast<const float4*>(&sw[jj0 + q][k4]);
            acc[q] += hv.x * wv.x + hv.y * wv.y + hv.z * wv.z + hv.w * wv.w;
        }
    }
    int node = node0 + r;
    if (node < n) {
        #pragma unroll
        for (int q = 0; q < 5; q++)
            out[(size_t)node * 40 + jj0 + q] = acc[q] + __ldg(&bout[jj0 + q]);
    }
}

// ---------------------------------------------------------------------------
extern "C" void kernel_launch(void* const* d_in, const int* in_sizes, int n_in,
                              void* d_out, int out_size) {
    const float* x = (const float*)d_in[0];
    const void* ei = d_in[1];
    const float* Wl1 = (const float*)d_in[2];
    const float* bl1 = (const float*)d_in[3];
    const float* Wr1 = (const float*)d_in[4];
    const float* Wl2 = (const float*)d_in[5];
    const float* bl2 = (const float*)d_in[6];
    const float* Wr2 = (const float*)d_in[7];
    const float* Wout = (const float*)d_in[8];
    const float* bout = (const float*)d_in[9];
    float* out = (float*)d_out;

    int n = in_sizes[0] / DIM;
    int e = in_sizes[1] / 2;

    static float* mean_f = nullptr;
    static float* h1_f = nullptr;
    static float* h2_f = nullptr;
    static uint2* xh_p = nullptr;
    static uint2* h1h_p = nullptr;
    if (!mean_f) {  // one-time symbol lookup + smem attribute (no allocation)
        void* p;
        cudaGetSymbolAddress(&p, g_mean4); mean_f = (float*)p;
        cudaGetSymbolAddress(&p, g_h14);   h1_f   = (float*)p;
        cudaGetSymbolAddress(&p, g_h24);   h2_f   = (float*)p;
        cudaGetSymbolAddress(&p, g_xh);    xh_p   = (uint2*)p;
        cudaGetSymbolAddress(&p, g_h1h);   h1h_p  = (uint2*)p;
        cudaFuncSetAttribute(gemm_mma_kernel,
                             cudaFuncAttributeMaxDynamicSharedMemorySize, SMEM_GEMM);
    }

    int eb = (e + 255) / 256;
    int nb = (n + 255) / 256;
    int sblk = (n + SCAN_BS - 1) / SCAN_BS;
    int n16 = n * 16;
    int cb = (n16 + 255) / 256;

    detect_kernel<<<1, 256>>>((const int*)ei, e);
    x2h_kernel<<<cb, 256>>>((const float4*)x, n16);
    clear_deg_kernel<<<nb, 256>>>(n);
    hist_kernel<<<eb, 256>>>(ei, e, n);
    scan_part_kernel<<<sblk, SCAN_BS>>>(n);
    scan_top_kernel<<<1, 1024>>>(sblk, n);
    scan_apply_kernel<<<sblk, SCAN_BS>>>(n);
    scatter_kernel<<<eb, 256>>>(ei, e, n);
    wprep_kernel<<<4, 256>>>(Wl1, Wr1, Wl2, Wr2);

    int ab = (n + 7) / 8;
    int gb = (n + 63) / 64;
    int ob = (n + 31) / 32;

    // Layer 1 (gather fp16 x; GEMM writes h1 + fp16 copy)
    aggregate_kernel<<<ab, 256>>>(xh_p, (float4*)mean_f, n);
    gemm_mma_kernel<<<gb, 256, SMEM_GEMM>>>(mean_f, x, 0, bl1, h1_f,
                                            (u32*)h1h_p, n, 1);
    // Layer 2 (gather fp16 h1)
    aggregate_kernel<<<ab, 256>>>(h1h_p, (float4*)mean_f, n);
    gemm_mma_kernel<<<gb, 256, SMEM_GEMM>>>(mean_f, h1_f, 4, bl2, h2_f,
                                            nullptr, n, 1);
    // Head
    out_gemm_kernel<<<ob, 256>>>(h2_f, Wout, bout, out, n);
}

// round 14
// speedup vs baseline: 1.1135x; 1.1080x over previous
#include <cuda_runtime.h>
#include <cuda_bf16.h>
#include <cuda_fp16.h>
#include <cstdint>

// GraphSAGE 2-layer + head.
// Edge phase: CSR build + warp-per-node fp16-gather mean aggregation.
// Layer GEMMs: PERSISTENT (grid=148, 1 CTA/SM) warp-level mma.sync bf16x3.
//   All 4 weight images loaded once per launch (was 218MB/launch re-copied);
//   A hi/lo double-buffered so conversion overlaps MMA.
// Head: bf16x3 mma on zero-padded 64-row Wout image.

#define MAXN 100000
#define MAXE 1600000
#define DIM  128
#define SCAN_BS 1024
#define MAX_BLKS 256

typedef unsigned int u32;
typedef unsigned long long u64;

// ---- bf16 image layout: row pitch 136 bf16 = 272B.
#define PITCHB 272
#define AIMG 17408                        // 64-row image (hi or lo)
#define BIMG 34816                        // 128-row image
// persistent GEMM smem: A buf0 hi/lo, A buf1 hi/lo, then 4 B images
#define PA(buf) ((buf) * 2 * AIMG)        // hi at PA, lo at PA+AIMG
#define PB (4 * AIMG)                     // 69632
#define SMEM_PGEMM (PB + 4 * BIMG)        // 208896
// head smem: A hi/lo (64 rows) + B hi/lo (64 rows)
#define H_AHI 0
#define H_ALO AIMG
#define H_BHI (2 * AIMG)
#define H_BLO (3 * AIMG)
#define SMEM_HEAD (4 * AIMG)              // 69632

__device__ int    g_is64;
__device__ int    g_deg[MAXN];
__device__ int    g_off[MAXN + 1];
__device__ int    g_cur[MAXN];
__device__ int    g_csr[MAXE];
__device__ int    g_part[MAX_BLKS];
__device__ float4 g_mean4[(size_t)MAXN * 32];
__device__ float4 g_h14[(size_t)MAXN * 32];
__device__ float4 g_h24[(size_t)MAXN * 32];
__device__ uint2  g_xh[(size_t)MAXN * 32];     // fp16 image of x
__device__ uint2  g_h1h[(size_t)MAXN * 32];    // fp16 image of h1
__device__ uint4  g_wimg[10][BIMG / 16];       // 0..7 layer W images, 8..9 Wout

// ---------------------------------------------------------------------------
__device__ __forceinline__ u32 smem_u32(const void* p) {
    u32 a;
    asm("{ .reg .u64 t; cvta.to.shared.u64 t, %1; cvt.u32.u64 %0, t; }"
        : "=r"(a) : "l"(p));
    return a;
}
__device__ __forceinline__ void ldsm4(u32& r0, u32& r1, u32& r2, u32& r3, u32 a) {
    asm volatile("ldmatrix.sync.aligned.m8n8.x4.shared.b16 {%0,%1,%2,%3}, [%4];"
                 : "=r"(r0), "=r"(r1), "=r"(r2), "=r"(r3) : "r"(a));
}
__device__ __forceinline__ void mma_bf16(float* d, const u32* a, u32 b0, u32 b1) {
    asm volatile(
        "mma.sync.aligned.m16n8k16.row.col.f32.bf16.bf16.f32 "
        "{%0,%1,%2,%3},{%4,%5,%6,%7},{%8,%9},{%0,%1,%2,%3};"
        : "+f"(d[0]), "+f"(d[1]), "+f"(d[2]), "+f"(d[3])
        : "r"(a[0]), "r"(a[1]), "r"(a[2]), "r"(a[3]), "r"(b0), "r"(b1));
}
__device__ __forceinline__ void cpa16(u32 s, const void* g) {
    asm volatile("cp.async.cg.shared.global [%0], [%1], 16;" :: "r"(s), "l"(g));
}
__device__ __forceinline__ void cpa_commit_wait() {
    asm volatile("cp.async.commit_group;" ::: "memory");
    asm volatile("cp.async.wait_group 0;" ::: "memory");
}
__device__ __forceinline__ void split2(float f0, float f1, u32& hp, u32& lp) {
    __nv_bfloat16 h0 = __float2bfloat16_rn(f0);
    __nv_bfloat16 h1 = __float2bfloat16_rn(f1);
    __nv_bfloat16 l0 = __float2bfloat16_rn(f0 - __bfloat162float(h0));
    __nv_bfloat16 l1 = __float2bfloat16_rn(f1 - __bfloat162float(h1));
    __nv_bfloat162 hh = __halves2bfloat162(h0, h1);
    __nv_bfloat162 ll = __halves2bfloat162(l0, l1);
    hp = *reinterpret_cast<u32*>(&hh);
    lp = *reinterpret_cast<u32*>(&ll);
}
__device__ __forceinline__ void split8(const float* f, u32* hp, u32* lp) {
    #pragma unroll
    for (int i = 0; i < 4; i++) split2(f[2 * i], f[2 * i + 1], hp[i], lp[i]);
}
__device__ __forceinline__ u32 h2bits(__half2 h) {
    return *reinterpret_cast<u32*>(&h);
}

// convert one 64-row fp32 slab -> bf16 hi/lo images at smem+abase / +AIMG
__device__ __forceinline__ void conv_slab(const float* __restrict__ A, int row0,
                                          int n, char* smem, int abase,
                                          int tid, int nthr) {
    for (int g = tid; g < 1024; g += nthr) {
        int row = g >> 4;
        int col8 = (g & 15) << 3;
        int gr = row0 + row;
        float f[8] = {0.f, 0.f, 0.f, 0.f, 0.f, 0.f, 0.f, 0.f};
        if (gr < n) {
            float4 v0 = *reinterpret_cast<const float4*>(&A[(size_t)gr * 128 + col8]);
            float4 v1 = *reinterpret_cast<const float4*>(&A[(size_t)gr * 128 + col8 + 4]);
            f[0] = v0.x; f[1] = v0.y; f[2] = v0.z; f[3] = v0.w;
            f[4] = v1.x; f[5] = v1.y; f[6] = v1.z; f[7] = v1.w;
        }
        u32 hp[4], lp[4];
        split8(f, hp, lp);
        int off = row * PITCHB + col8 * 2;
        *reinterpret_cast<uint4*>(smem + abase + off) =
            make_uint4(hp[0], hp[1], hp[2], hp[3]);
        *reinterpret_cast<uint4*>(smem + abase + AIMG + off) =
            make_uint4(lp[0], lp[1], lp[2], lp[3]);
    }
}

// ---------------------------------------------------------------------------
// edge-index dtype detection (JAX silently demotes int64 randint to int32)
// ---------------------------------------------------------------------------
__global__ void detect_kernel(const int* __restrict__ w, int e) {
    __shared__ int bad;
    int i = threadIdx.x;
    if (i == 0) bad = 0;
    __syncthreads();
    int nchk = (e < 256) ? e : 256;
    if (i < nchk && w[2 * i + 1] != 0) atomicOr(&bad, 1);
    __syncthreads();
    if (i == 0) g_is64 = bad ? 0 : 1;
}

__global__ void clear_deg_kernel(int n) {
    int i = blockIdx.x * blockDim.x + threadIdx.x;
    if (i < n) g_deg[i] = 0;
}

__global__ void hist_kernel(const void* __restrict__ ei, int e, int n) {
    int i = blockIdx.x * blockDim.x + threadIdx.x;
    if (i >= e) return;
    int d = g_is64 ? (int)((const long long*)ei)[e + i] : ((const int*)ei)[e + i];
    if ((unsigned)d < (unsigned)n) atomicAdd(&g_deg[d], 1);
}

// ---------------------------------------------------------------------------
// 3-phase parallel scan
// ---------------------------------------------------------------------------
__global__ void scan_part_kernel(int n) {
    __shared__ int ws[32];
    int i = blockIdx.x * SCAN_BS + threadIdx.x;
    int lane = threadIdx.x & 31, wid = threadIdx.x >> 5;
    int v = (i < n) ? g_deg[i] : 0;
    #pragma unroll
    for (int d = 16; d; d >>= 1) v += __shfl_down_sync(0xffffffffu, v, d);
    if (lane == 0) ws[wid] = v;
    __syncthreads();
    if (wid == 0) {
        int t = ws[lane];
        #pragma unroll
        for (int d = 16; d; d >>= 1) t += __shfl_down_sync(0xffffffffu, t, d);
        if (lane == 0) g_part[blockIdx.x] = t;
    }
}

__global__ void scan_top_kernel(int nblk, int n) {
    __shared__ int wsum[32];
    int tid = threadIdx.x, lane = tid & 31, wid = tid >> 5;
    int v = (tid < nblk) ? g_part[tid] : 0;
    int s = v;
    #pragma unroll
    for (int d = 1; d < 32; d <<= 1) {
        int t = __shfl_up_sync(0xffffffffu, s, d);
        if (lane >= d) s += t;
    }
    if (lane == 31) wsum[wid] = s;
    __syncthreads();
    if (wid == 0) {
        int w2 = wsum[lane];
        #pragma unroll
        for (int d = 1; d < 32; d <<= 1) {
            int t = __shfl_up_sync(0xffffffffu, w2, d);
            if (lane >= d) w2 += t;
        }
        wsum[lane] = w2;
    }
    __syncthreads();
    int warp_base = (wid > 0) ? wsum[wid - 1] : 0;
    int incl = warp_base + s;
    if (tid < nblk) g_part[tid] = incl - v;
    if (tid == 1023) g_off[n] = incl;
}

__global__ void scan_apply_kernel(int n) {
    __shared__ int wsum[32];
    int tid = threadIdx.x, lane = tid & 31, wid = tid >> 5;
    int i = blockIdx.x * SCAN_BS + tid;
    int v = (i < n) ? g_deg[i] : 0;
    int s = v;
    #pragma unroll
    for (int d = 1; d < 32; d <<= 1) {
        int t = __shfl_up_sync(0xffffffffu, s, d);
        if (lane >= d) s += t;
    }
    if (lane == 31) wsum[wid] = s;
    __syncthreads();
    if (wid == 0) {
        int w2 = wsum[lane];
        #pragma unroll
        for (int d = 1; d < 32; d <<= 1) {
            int t = __shfl_up_sync(0xffffffffu, w2, d);
            if (lane >= d) w2 += t;
        }
        wsum[lane] = w2;
    }
    __syncthreads();
    int warp_base = (wid > 0) ? wsum[wid - 1] : 0;
    int excl = g_part[blockIdx.x] + warp_base + s - v;
    if (i < n) { g_off[i] = excl; g_cur[i] = excl; }
}

__global__ void scatter_kernel(const void* __restrict__ ei, int e, int n) {
    int i = blockIdx.x * blockDim.x + threadIdx.x;
    if (i >= e) return;
    int s, d;
    if (g_is64) {
        s = (int)((const long long*)ei)[i];
        d = (int)((const long long*)ei)[e + i];
    } else {
        s = ((const int*)ei)[i];
        d = ((const int*)ei)[e + i];
    }
    if ((unsigned)d >= (unsigned)n || (unsigned)s >= (unsigned)n) return;
    int pos = atomicAdd(&g_cur[d], 1);
    g_csr[pos] = s;
}

// ---------------------------------------------------------------------------
// x -> fp16 image
// ---------------------------------------------------------------------------
__global__ void x2h_kernel(const float4* __restrict__ x, int n16) {
    int i = blockIdx.x * blockDim.x + threadIdx.x;
    if (i >= n16) return;
    float4 v0 = x[2 * i], v1 = x[2 * i + 1];
    uint2 o0, o1;
    o0.x = h2bits(__floats2half2_rn(v0.x, v0.y));
    o0.y = h2bits(__floats2half2_rn(v0.z, v0.w));
    o1.x = h2bits(__floats2half2_rn(v1.x, v1.y));
    o1.y = h2bits(__floats2half2_rn(v1.z, v1.w));
    g_xh[2 * i] = o0;
    g_xh[2 * i + 1] = o1;
}

// ---------------------------------------------------------------------------
// mean aggregation over fp16 rows: one warp per dst node, unroll-8 gather
// ---------------------------------------------------------------------------
__global__ void aggregate_kernel(const uint2* __restrict__ feat,
                                 float4* __restrict__ outp, int n) {
    int w = (blockIdx.x * blockDim.x + threadIdx.x) >> 5;
    int lane = threadIdx.x & 31;
    if (w >= n) return;
    int s0 = g_off[w], s1 = g_off[w + 1];
    float4 a = make_float4(0.f, 0.f, 0.f, 0.f);
    int e = s0;
    for (; e + 8 <= s1; e += 8) {
        uint2 u[8];
        #pragma unroll
        for (int q = 0; q < 8; q++)
            u[q] = feat[(size_t)g_csr[e + q] * 32 + lane];
        #pragma unroll
        for (int q = 0; q < 8; q++) {
            float2 f0 = __half22float2(*reinterpret_cast<__half2*>(&u[q].x));
            float2 f1 = __half22float2(*reinterpret_cast<__half2*>(&u[q].y));
            a.x += f0.x; a.y += f0.y; a.z += f1.x; a.w += f1.y;
        }
    }
    for (; e < s1; e++) {
        uint2 u = feat[(size_t)g_csr[e] * 32 + lane];
        float2 f0 = __half22float2(*reinterpret_cast<__half2*>(&u.x));
        float2 f1 = __half22float2(*reinterpret_cast<__half2*>(&u.y));
        a.x += f0.x; a.y += f0.y; a.z += f1.x; a.w += f1.y;
    }
    int deg = s1 - s0;
    float inv = 1.0f / (float)(deg > 1 ? deg : 1);
    a.x *= inv; a.y *= inv; a.z *= inv; a.w *= inv;
    outp[(size_t)w * 32 + lane] = a;
}

// ---------------------------------------------------------------------------
// weight prep: bf16 hi/lo pitch-136 images. blocks 0-3: 128x128 layer
// weights; block 4: Wout (40x128) zero-padded to 64 rows.
// ---------------------------------------------------------------------------
__global__ void wprep_kernel(const float* __restrict__ Wl1,
                             const float* __restrict__ Wr1,
                             const float* __restrict__ Wl2,
                             const float* __restrict__ Wr2,
                             const float* __restrict__ Wout) {
    const float* Wm[5] = {Wl1, Wr1, Wl2, Wr2, Wout};
    int m = blockIdx.x;
    const float* W = Wm[m];
    int rows = (m == 4) ? 40 : 128;
    int rows_img = (m == 4) ? 64 : 128;
    char* hi_img = (char*)&g_wimg[2 * m][0];
    char* lo_img = (char*)&g_wimg[2 * m + 1][0];
    for (int g = threadIdx.x; g < rows_img * 16; g += blockDim.x) {
        int row = g >> 4;
        int col8 = (g & 15) << 3;
        float f[8] = {0.f, 0.f, 0.f, 0.f, 0.f, 0.f, 0.f, 0.f};
        if (row < rows) {
            #pragma unroll
            for (int i = 0; i < 8; i++) f[i] = W[row * 128 + col8 + i];
        }
        u32 hp[4], lp[4];
        split8(f, hp, lp);
        int off = row * PITCHB + col8 * 2;
        *reinterpret_cast<uint4*>(hi_img + off) = make_uint4(hp[0], hp[1], hp[2], hp[3]);
        *reinterpret_cast<uint4*>(lo_img + off) = make_uint4(lp[0], lp[1], lp[2], lp[3]);
    }
}

// ---------------------------------------------------------------------------
// PERSISTENT dual GEMM: C = relu(A1@Wl^T + A2@Wr^T + bias).
// grid = min(148, ntiles), 512 threads, warp grid 4x4, warp tile 16x32,
// M-tile 64. B images (4x34KB) loaded ONCE; A hi/lo double-buffered so
// conversion of the next (tile,phase) overlaps MMA of the current one.
// ---------------------------------------------------------------------------
__global__ __launch_bounds__(512) void gemm_pers_kernel(
    const float* __restrict__ A1, const float* __restrict__ A2,
    int imgbase, const float* __restrict__ bias,
    float* __restrict__ C, u32* __restrict__ Ch, int n, int ntiles) {
    extern __shared__ __align__(16) char smem[];
    u32 sbase = smem_u32(smem);
    int tid = threadIdx.x, wid = tid >> 5, lane = tid & 31;
    int wr = (wid >> 2) * 16;          // warp row offset (0,16,32,48)
    int wc = (wid & 3) * 32;           // warp col offset (0,32,64,96)
    int bid = blockIdx.x, G = gridDim.x;

    // ---- load all 4 B images once ----
    #pragma unroll
    for (int im = 0; im < 4; im++) {
        const uint4* b = g_wimg[imgbase + im];
        for (int g = tid; g < BIMG / 16; g += 512)
            cpa16(sbase + PB + im * BIMG + g * 16, b + g);
    }
    cpa_commit_wait();

    int ntl = (ntiles > bid) ? (ntiles - bid + G - 1) / G : 0;
    int Wtot = 2 * ntl;
    if (Wtot == 0) return;

    float acc[4][4];
    #pragma unroll
    for (int b = 0; b < 4; b++)
        #pragma unroll
        for (int c = 0; c < 4; c++) acc[b][c] = 0.f;

    // prologue: convert item 0 (tile=bid, phase 0 -> A1) into buf 0
    conv_slab(A1, bid * 64, n, smem, PA(0), tid, 512);

    int lr = lane & 15;
    int lc = (lane >> 4) * 8;

    #pragma unroll 1
    for (int w = 0; w < Wtot; w++) {
        __syncthreads();               // conv for item w complete
        int p = w & 1;
        int tile = bid + (w >> 1) * G;
        // convert next item (overlaps with MMA below)
        if (w + 1 < Wtot) {
            int p2 = (w + 1) & 1;
            int t2 = bid + ((w + 1) >> 1) * G;
            conv_slab(p2 ? A2 : A1, t2 * 64, n, smem, PA(p2), tid, 512);
        }
        // ---- MMA over K for item w ----
        u32 abase = sbase + PA(p);
        u32 bbase = sbase + PB + p * 2 * BIMG;
        #pragma unroll 1
        for (int k0 = 0; k0 < 128; k0 += 16) {
            u32 ah[4], al[4], bh[2][4], bl[2][4];
            u32 ad = abase + (wr + lr) * PITCHB + (k0 + lc) * 2;
            ldsm4(ah[0], ah[1], ah[2], ah[3], ad);
            ldsm4(al[0], al[1], al[2], al[3], ad + AIMG);
            #pragma unroll
            for (int q = 0; q < 2; q++) {
                u32 bd = bbase + (wc + q * 16 + lr) * PITCHB + (k0 + lc) * 2;
                ldsm4(bh[q][0], bh[q][1], bh[q][2], bh[q][3], bd);
                ldsm4(bl[q][0], bl[q][1], bl[q][2], bl[q][3], bd + BIMG);
            }
            #pragma unroll
            for (int nf = 0; nf < 4; nf++) {
                int q = nf >> 1, h = nf & 1;
                mma_bf16(acc[nf], ah, bh[q][h], bh[q][h + 2]);
                mma_bf16(acc[nf], al, bh[q][h], bh[q][h + 2]);
                mma_bf16(acc[nf], ah, bl[q][h], bl[q][h + 2]);
            }
        }
        // ---- epilogue after phase 1 ----
        if (p == 1) {
            int rb = tile * 64 + wr + (lane >> 2);
            #pragma unroll
            for (int nf = 0; nf < 4; nf++) {
                int cn = wc + nf * 8 + (lane & 3) * 2;
                float b0 = __ldg(&bias[cn]), b1 = __ldg(&bias[cn + 1]);
                float v0 = acc[nf][0] + b0, v1 = acc[nf][1] + b1;
                float v2 = acc[nf][2] + b0, v3 = acc[nf][3] + b1;
                v0 = v0 < 0.f ? 0.f : v0; v1 = v1 < 0.f ? 0.f : v1;
                v2 = v2 < 0.f ? 0.f : v2; v3 = v3 < 0.f ? 0.f : v3;
                if (rb < n) {
                    *reinterpret_cast<float2*>(&C[(size_t)rb * 128 + cn]) =
                        make_float2(v0, v1);
                    if (Ch) Ch[(size_t)rb * 64 + (cn >> 1)] =
                        h2bits(__floats2half2_rn(v0, v1));
                }
                if (rb + 8 < n) {
                    *reinterpret_cast<float2*>(&C[(size_t)(rb + 8) * 128 + cn]) =
                        make_float2(v2, v3);
                    if (Ch) Ch[(size_t)(rb + 8) * 64 + (cn >> 1)] =
                        h2bits(__floats2half2_rn(v2, v3));
                }
                acc[nf][0] = acc[nf][1] = acc[nf][2] = acc[nf][3] = 0.f;
            }
        }
    }
}

// ---------------------------------------------------------------------------
// head via mma: out[N,40] = h2 @ Wout^T + bout (Wout padded to 64 rows).
// 256 threads, 8 warps (4x2), warp tile 16x32, M-tile 64, single phase.
// ---------------------------------------------------------------------------
__global__ __launch_bounds__(256) void head_mma_kernel(
    const float* __restrict__ h, const float* __restrict__ bout,
    float* __restrict__ out, int n) {
    extern __shared__ __align__(16) char smem[];
    u32 sbase = smem_u32(smem);
    int tid = threadIdx.x, wid = tid >> 5, lane = tid & 31;
    int row0 = blockIdx.x * 64;
    int wr = (wid >> 1) * 16;          // 0,16,32,48
    int wc = (wid & 1) * 32;           // 0,32

    // B images (Wout hi/lo, 64 rows)
    for (int g = tid; g < AIMG / 16; g += 256) {
        cpa16(sbase + H_BHI + g * 16, &g_wimg[8][g]);
        cpa16(sbase + H_BLO + g * 16, &g_wimg[9][g]);
    }
    conv_slab(h, row0, n, smem, H_AHI, tid, 256);
    cpa_commit_wait();
    __syncthreads();

    float acc[4][4];
    #pragma unroll
    for (int b = 0; b < 4; b++)
        #pragma unroll
        for (int c = 0; c < 4; c++) acc[b][c] = 0.f;

    int lr = lane & 15;
    int lc = (lane >> 4) * 8;
    #pragma unroll 1
    for (int k0 = 0; k0 < 128; k0 += 16) {
        u32 ah[4], al[4], bh[2][4], bl[2][4];
        u32 ad = sbase + H_AHI + (wr + lr) * PITCHB + (k0 + lc) * 2;
        ldsm4(ah[0], ah[1], ah[2], ah[3], ad);
        ldsm4(al[0], al[1], al[2], al[3], ad + AIMG);
        #pragma unroll
        for (int q = 0; q < 2; q++) {
            u32 bd = sbase + H_BHI + (wc + q * 16 + lr) * PITCHB + (k0 + lc) * 2;
            ldsm4(bh[q][0], bh[q][1], bh[q][2], bh[q][3], bd);
            ldsm4(bl[q][0], bl[q][1], bl[q][2], bl[q][3], bd + AIMG);
        }
        #pragma unroll
        for (int nf = 0; nf < 4; nf++) {
            int q = nf >> 1, hh = nf & 1;
            mma_bf16(acc[nf], ah, bh[q][hh], bh[q][hh + 2]);
            mma_bf16(acc[nf], al, bh[q][hh], bh[q][hh + 2]);
            mma_bf16(acc[nf], ah, bl[q][hh], bl[q][hh + 2]);
        }
    }

    int rb = row0 + wr + (lane >> 2);
    #pragma unroll
    for (int nf = 0; nf < 4; nf++) {
        int cn = wc + nf * 8 + (lane & 3) * 2;
        if (cn < 40) {
            float b0 = __ldg(&bout[cn]), b1 = __ldg(&bout[cn + 1]);
            if (rb < n)
                *reinterpret_cast<float2*>(&out[(size_t)rb * 40 + cn]) =
                    make_float2(acc[nf][0] + b0, acc[nf][1] + b1);
            if (rb + 8 < n)
                *reinterpret_cast<float2*>(&out[(size_t)(rb + 8) * 40 + cn]) =
                    make_float2(acc[nf][2] + b0, acc[nf][3] + b1);
        }
    }
}

// ---------------------------------------------------------------------------
extern "C" void kernel_launch(void* const* d_in, const int* in_sizes, int n_in,
                              void* d_out, int out_size) {
    const float* x = (const float*)d_in[0];
    const void* ei = d_in[1];
    const float* Wl1 = (const float*)d_in[2];
    const float* bl1 = (const float*)d_in[3];
    const float* Wr1 = (const float*)d_in[4];
    const float* Wl2 = (const float*)d_in[5];
    const float* bl2 = (const float*)d_in[6];
    const float* Wr2 = (const float*)d_in[7];
    const float* Wout = (const float*)d_in[8];
    const float* bout = (const float*)d_in[9];
    float* out = (float*)d_out;

    int n = in_sizes[0] / DIM;
    int e = in_sizes[1] / 2;

    static float* mean_f = nullptr;
    static float* h1_f = nullptr;
    static float* h2_f = nullptr;
    static uint2* xh_p = nullptr;
    static uint2* h1h_p = nullptr;
    if (!mean_f) {  // one-time symbol lookup + smem attributes (no allocation)
        void* p;
        cudaGetSymbolAddress(&p, g_mean4); mean_f = (float*)p;
        cudaGetSymbolAddress(&p, g_h14);   h1_f   = (float*)p;
        cudaGetSymbolAddress(&p, g_h24);   h2_f   = (float*)p;
        cudaGetSymbolAddress(&p, g_xh);    xh_p   = (uint2*)p;
        cudaGetSymbolAddress(&p, g_h1h);   h1h_p  = (uint2*)p;
        cudaFuncSetAttribute(gemm_pers_kernel,
                             cudaFuncAttributeMaxDynamicSharedMemorySize, SMEM_PGEMM);
        cudaFuncSetAttribute(head_mma_kernel,
                             cudaFuncAttributeMaxDynamicSharedMemorySize, SMEM_HEAD);
    }

    int eb = (e + 255) / 256;
    int nb = (n + 255) / 256;
    int sblk = (n + SCAN_BS - 1) / SCAN_BS;
    int n16 = n * 16;
    int cb = (n16 + 255) / 256;

    detect_kernel<<<1, 256>>>((const int*)ei, e);
    x2h_kernel<<<cb, 256>>>((const float4*)x, n16);
    clear_deg_kernel<<<nb, 256>>>(n);
    hist_kernel<<<eb, 256>>>(ei, e, n);
    scan_part_kernel<<<sblk, SCAN_BS>>>(n);
    scan_top_kernel<<<1, 1024>>>(sblk, n);
    scan_apply_kernel<<<sblk, SCAN_BS>>>(n);
    scatter_kernel<<<eb, 256>>>(ei, e, n);
    wprep_kernel<<<5, 256>>>(Wl1, Wr1, Wl2, Wr2, Wout);

    int ab = (n + 7) / 8;
    int ntiles = (n + 63) / 64;
    int pg = (ntiles < 148) ? ntiles : 148;
    int hb = ntiles;

    // Layer 1 (gather fp16 x; GEMM writes h1 + fp16 copy)
    aggregate_kernel<<<ab, 256>>>(xh_p, (float4*)mean_f, n);
    gemm_pers_kernel<<<pg, 512, SMEM_PGEMM>>>(mean_f, x, 0, bl1, h1_f,
                                              (u32*)h1h_p, n, ntiles);
    // Layer 2 (gather fp16 h1)
    aggregate_kernel<<<ab, 256>>>(h1h_p, (float4*)mean_f, n);
    gemm_pers_kernel<<<pg, 512, SMEM_PGEMM>>>(mean_f, h1_f, 4, bl2, h2_f,
                                              nullptr, n, ntiles);
    // Head (tensor cores, Wout padded to 64 rows)
    head_mma_kernel<<<hb, 256, SMEM_HEAD>>>(h2_f, bout, out, n);
}